// round 7
// baseline (speedup 1.0000x reference)
#include <cuda_runtime.h>
#include <cuda_fp16.h>
#include <cstdint>

#define NROW 12288
#define INF  128
#define OUTF 64
#define LOG2E 1.44269504088896341f
#define NCHUNK 6
#define CT 16                     // tiles per chunk (16*128 = 2048 cols)
#define NITILE (NROW / 128)       // 96
#define NUNITS (NITILE * NCHUNK)  // 576
#define GRID 148

// smem layout (bytes)
#define ADJ0 0
#define ADJ1 65536
#define A0   131072
#define A1   163840               // A_SZ = 32768 (128 rows x 256B, xor-swizzled)
#define B0   196608
#define B1   212992               // B_SZ = 16384 (64 rows x 256B, xor-swizzled)
#define SMEM_BYTES 229376

// ---------------- device scratch ----------------
__device__ float  g_wh1[NROW];
__device__ float  g_wh2[NROW];
__device__ float  g_wh2max;
__device__ __half g_hT[OUTF * NROW];          // h transposed fp16 [f][j]
__device__ float  g_S[NCHUNK][NROW * OUTF];   // partial E'@h per chunk
__device__ float  g_L[NCHUNK][NROW];          // partial row sums per chunk

// ---------------- Kernel A: h = input@W, wh1/wh2, hT ----------------
__global__ void kA(const float* __restrict__ inp, const float* __restrict__ W,
                   const float* __restrict__ a) {
    __shared__ float in_s[4][INF];
    __shared__ float red1[8], red2[8];
    int tid = threadIdx.x;
    int i0 = blockIdx.x * 4;
    for (int e = tid; e < 4 * INF; e += 256)
        in_s[e >> 7][e & 127] = inp[(i0 + (e >> 7)) * INF + (e & 127)];
    __syncthreads();
    int f = tid & 63, r = tid >> 6;
    float acc = 0.f;
#pragma unroll 8
    for (int k = 0; k < INF; k++)
        acc = fmaf(in_s[r][k], W[k * OUTF + f], acc);
    int i = i0 + r;
    g_hT[f * NROW + i] = __float2half(acc);
    float p1 = acc * a[f];
    float p2 = acc * a[64 + f];
#pragma unroll
    for (int o = 16; o > 0; o >>= 1) {
        p1 += __shfl_xor_sync(~0u, p1, o);
        p2 += __shfl_xor_sync(~0u, p2, o);
    }
    int w = tid >> 5;
    if ((tid & 31) == 0) { red1[w] = p1; red2[w] = p2; }
    __syncthreads();
    if (tid < 4) {
        g_wh1[i0 + tid] = red1[2 * tid] + red1[2 * tid + 1];
        g_wh2[i0 + tid] = red2[2 * tid] + red2[2 * tid + 1];
    }
}

// ---------------- Kernel A2: global max of wh2 ----------------
__global__ void kMax() {
    __shared__ float red[8];
    int tid = threadIdx.x;
    float m = -1e30f;
    for (int i = tid; i < NROW; i += 256) m = fmaxf(m, g_wh2[i]);
#pragma unroll
    for (int o = 16; o > 0; o >>= 1) m = fmaxf(m, __shfl_xor_sync(~0u, m, o));
    if ((tid & 31) == 0) red[tid >> 5] = m;
    __syncthreads();
    if (tid == 0) {
        float mm = red[0];
#pragma unroll
        for (int w = 1; w < 8; w++) mm = fmaxf(mm, red[w]);
        g_wh2max = mm;
    }
}

// pad so ncu's capture (launch index 3) lands on kMain
__global__ void kPad() {}

__device__ __forceinline__ void cp_async16(uint32_t dst, const void* src) {
    asm volatile("cp.async.cg.shared.global [%0], [%1], 16;\n" :: "r"(dst), "l"(src));
}

// ---------------- Kernel B: persistent warp-specialized, cp.async adj ----------------
// 384 threads: warps 0-7 build, warps 8-11 MMA.
__global__ void __launch_bounds__(384, 1) kMain(const int* __restrict__ adj) {
    extern __shared__ char smem[];
    uint32_t sb = (uint32_t)__cvta_generic_to_shared(smem);
    int tid = threadIdx.x, lane = tid & 31, w = tid >> 5;
    const float wh2max = g_wh2max;
    const uint32_t* hTu = (const uint32_t*)g_hT;

    if (w < 8) {
        // ================= builders (256 threads) =================
        int rowbase = w * 16;
        int cprow = tid >> 1, cphalf = tid & 1;      // cp.async: 256B per thread
        int l2 = lane >> 1, lo8 = (lane & 1) * 8;
        int jp = tid & 63, n0 = tid >> 6;            // B-build mapping
        uint32_t Apart = (uint32_t)(rowbase * 256);
        int gt = 0;

        for (int u = blockIdx.x; u < NUNITS; u += GRID) {
            int itile = u / NCHUNK, chunk = u % NCHUNK;
            int i0 = itile * 128;
            int jbase = chunk * (CT * 128);

            // unit prologue: prefetch tile 0 into adj buf 0
            {
                const int* src = adj + (long long)(i0 + cprow) * NROW + jbase + cphalf * 64;
                uint32_t dst = sb + ADJ0 + (uint32_t)(cprow * 512 + cphalf * 256);
#pragma unroll
                for (int k = 0; k < 16; k++) cp_async16(dst + k * 16, src + k * 4);
                asm volatile("cp.async.commit_group;");
            }

            float w1r[16], m2r[16], racc[16];
#pragma unroll
            for (int rr = 0; rr < 16; rr++) {
                float w1 = g_wh1[i0 + rowbase + rr];
                float s = w1 + wh2max;
                float m = fmaxf(s, 0.2f * s);     // lrelu upper bound of row max
                w1r[rr] = w1;
                m2r[rr] = m * LOG2E;
                racc[rr] = 0.f;
            }

            for (int t = 0; t < CT; t++) {
                int b = t & 1;
                int j0 = jbase + t * 128;

                // B-operand gmem loads (L2-resident hT), issued early
                uint32_t bwd[16];
                int j0h = j0 >> 1;
#pragma unroll
                for (int s = 0; s < 16; s++)
                    bwd[s] = __ldg(&hTu[(n0 + 4 * s) * (NROW / 2) + j0h + jp]);

                asm volatile("cp.async.wait_group 0;");          // own copies of tile t done
                asm volatile("bar.sync 5, 256;");                // all copies visible; t-1 reads done

                if (t + 1 < CT) {                                // prefetch t+1
                    const int* src = adj + (long long)(i0 + cprow) * NROW + j0 + 128 + cphalf * 64;
                    uint32_t dst = sb + (((t + 1) & 1) ? ADJ1 : ADJ0) +
                                   (uint32_t)(cprow * 512 + cphalf * 256);
#pragma unroll
                    for (int k = 0; k < 16; k++) cp_async16(dst + k * 16, src + k * 4);
                    asm volatile("cp.async.commit_group;");
                }

                if (gt >= 2) asm volatile("bar.sync %0, 384;" :: "r"(3 + b));

                uint32_t adjb = sb + (b ? ADJ1 : ADJ0);
                uint32_t Abuf = sb + (b ? A1 : A0) + Apart;
                float4 wv = *(const float4*)(g_wh2 + j0 + lane * 4);
#pragma unroll
                for (int rr = 0; rr < 16; rr++) {
                    int av0, av1, av2, av3;
                    asm volatile("ld.shared.v4.b32 {%0,%1,%2,%3}, [%4];"
                                 : "=r"(av0), "=r"(av1), "=r"(av2), "=r"(av3)
                                 : "r"(adjb + (uint32_t)((rowbase + rr) * 512 + lane * 16)));
                    float w1 = w1r[rr], m2 = m2r[rr];
                    float s0 = w1 + wv.x, s1 = w1 + wv.y, s2 = w1 + wv.z, s3 = w1 + wv.w;
                    float x0 = fmaf(fmaxf(s0, 0.2f * s0), LOG2E, -m2);
                    float x1 = fmaf(fmaxf(s1, 0.2f * s1), LOG2E, -m2);
                    float x2 = fmaf(fmaxf(s2, 0.2f * s2), LOG2E, -m2);
                    float x3 = fmaf(fmaxf(s3, 0.2f * s3), LOG2E, -m2);
                    x0 = av0 ? x0 : -1e4f;
                    x1 = av1 ? x1 : -1e4f;
                    x2 = av2 ? x2 : -1e4f;
                    x3 = av3 ? x3 : -1e4f;
                    __half2 p01 = __floats2half2_rn(x0, x1);
                    __half2 p23 = __floats2half2_rn(x2, x3);
                    uint32_t u01 = *(uint32_t*)&p01;
                    uint32_t u23 = *(uint32_t*)&p23;
                    uint32_t e01, e23;
                    asm("ex2.approx.f16x2 %0, %1;" : "=r"(e01) : "r"(u01));
                    asm("ex2.approx.f16x2 %0, %1;" : "=r"(e23) : "r"(u23));
                    float2 f01 = __half22float2(*(__half2*)&e01);
                    float2 f23 = __half22float2(*(__half2*)&e23);
                    racc[rr] += (f01.x + f01.y) + (f23.x + f23.y);
                    uint32_t sw = (uint32_t)(((l2 ^ ((rr & 7) << 1)) << 4) + lo8);
                    asm volatile("st.shared.v2.b32 [%0], {%1,%2};"
                                 :: "r"(Abuf + (uint32_t)(rr * 256) + sw), "r"(e01), "r"(e23));
                }
                // B store (xor-swizzled)
                uint32_t Bbuf = sb + (b ? B1 : B0);
#pragma unroll
                for (int s = 0; s < 16; s++) {
                    int n = n0 + 4 * s;
                    uint32_t sw = (uint32_t)((((jp >> 2) ^ ((n & 7) << 1)) << 4) + (jp & 3) * 4);
                    asm volatile("st.shared.b32 [%0], %1;"
                                 :: "r"(Bbuf + (uint32_t)(n * 256) + sw), "r"(bwd[s]));
                }
                asm volatile("membar.cta;" ::: "memory");
                asm volatile("bar.arrive %0, 384;" :: "r"(1 + b));
                gt++;
            }

            // row-sum reduce + store
#pragma unroll
            for (int rr = 0; rr < 16; rr++) {
                float v = racc[rr];
#pragma unroll
                for (int o = 16; o > 0; o >>= 1) v += __shfl_xor_sync(~0u, v, o);
                if (lane == rr) g_L[chunk][i0 + rowbase + rr] = v;
            }
        }
    } else {
        // ================= MMA warps (128 threads) =================
        int mw = w - 8;                    // 0..3 -> rows mw*32..+31
        int r15 = lane & 15;
        int rx = (lane & 7) << 1;          // A xor key
        int c0 = lane >> 4;                // A col half
        int g2 = lane >> 4, kh = (lane >> 3) & 1, r7 = lane & 7;
        int rxb = r7 << 1;                 // B xor key
        uint32_t arow0 = (uint32_t)((mw * 32 + r15) * 256);
        uint32_t arow1 = arow0 + 16 * 256;
        uint32_t brow[4];
#pragma unroll
        for (int nt2 = 0; nt2 < 4; nt2++)
            brow[nt2] = (uint32_t)((nt2 * 16 + g2 * 8 + r7) * 256);

        for (int u = blockIdx.x; u < NUNITS; u += GRID) {
            int itile = u / NCHUNK, chunk = u % NCHUNK;
            int i0 = itile * 128;

            float acc[2][8][4];
#pragma unroll
            for (int mt = 0; mt < 2; mt++)
#pragma unroll
                for (int nt = 0; nt < 8; nt++)
#pragma unroll
                    for (int q = 0; q < 4; q++) acc[mt][nt][q] = 0.f;

            for (int t = 0; t < CT; t++) {
                int b = t & 1;
                asm volatile("bar.sync %0, 384;" :: "r"(1 + b));
                uint32_t Ab = sb + (b ? A1 : A0);
                uint32_t Bb = sb + (b ? B1 : B0);
#pragma unroll
                for (int ks = 0; ks < 8; ks++) {
                    uint32_t aswz = (uint32_t)((((ks * 2 + c0) ^ rx) << 4));
                    uint32_t a0, a1, a2, a3, a4, a5, a6, a7;
                    asm volatile("ldmatrix.sync.aligned.m8n8.x4.shared.b16 {%0,%1,%2,%3}, [%4];"
                                 : "=r"(a0), "=r"(a1), "=r"(a2), "=r"(a3)
                                 : "r"(Ab + arow0 + aswz));
                    asm volatile("ldmatrix.sync.aligned.m8n8.x4.shared.b16 {%0,%1,%2,%3}, [%4];"
                                 : "=r"(a4), "=r"(a5), "=r"(a6), "=r"(a7)
                                 : "r"(Ab + arow1 + aswz));
                    uint32_t bswz = (uint32_t)((((ks * 2 + kh) ^ rxb) << 4));
#pragma unroll
                    for (int nt2 = 0; nt2 < 4; nt2++) {
                        uint32_t b0, b1, b2, b3;
                        asm volatile("ldmatrix.sync.aligned.m8n8.x4.shared.b16 {%0,%1,%2,%3}, [%4];"
                                     : "=r"(b0), "=r"(b1), "=r"(b2), "=r"(b3)
                                     : "r"(Bb + brow[nt2] + bswz));
                        int nt = nt2 * 2;
                        asm volatile("mma.sync.aligned.m16n8k16.row.col.f32.f16.f16.f32 "
                                     "{%0,%1,%2,%3}, {%4,%5,%6,%7}, {%8,%9}, {%0,%1,%2,%3};"
                                     : "+f"(acc[0][nt][0]), "+f"(acc[0][nt][1]),
                                       "+f"(acc[0][nt][2]), "+f"(acc[0][nt][3])
                                     : "r"(a0), "r"(a1), "r"(a2), "r"(a3), "r"(b0), "r"(b1));
                        asm volatile("mma.sync.aligned.m16n8k16.row.col.f32.f16.f16.f32 "
                                     "{%0,%1,%2,%3}, {%4,%5,%6,%7}, {%8,%9}, {%0,%1,%2,%3};"
                                     : "+f"(acc[1][nt][0]), "+f"(acc[1][nt][1]),
                                       "+f"(acc[1][nt][2]), "+f"(acc[1][nt][3])
                                     : "r"(a4), "r"(a5), "r"(a6), "r"(a7), "r"(b0), "r"(b1));
                        asm volatile("mma.sync.aligned.m16n8k16.row.col.f32.f16.f16.f32 "
                                     "{%0,%1,%2,%3}, {%4,%5,%6,%7}, {%8,%9}, {%0,%1,%2,%3};"
                                     : "+f"(acc[0][nt + 1][0]), "+f"(acc[0][nt + 1][1]),
                                       "+f"(acc[0][nt + 1][2]), "+f"(acc[0][nt + 1][3])
                                     : "r"(a0), "r"(a1), "r"(a2), "r"(a3), "r"(b2), "r"(b3));
                        asm volatile("mma.sync.aligned.m16n8k16.row.col.f32.f16.f16.f32 "
                                     "{%0,%1,%2,%3}, {%4,%5,%6,%7}, {%8,%9}, {%0,%1,%2,%3};"
                                     : "+f"(acc[1][nt + 1][0]), "+f"(acc[1][nt + 1][1]),
                                       "+f"(acc[1][nt + 1][2]), "+f"(acc[1][nt + 1][3])
                                     : "r"(a4), "r"(a5), "r"(a6), "r"(a7), "r"(b2), "r"(b3));
                    }
                }
                asm volatile("bar.arrive %0, 384;" :: "r"(3 + b));
            }

            // unit epilogue: dump accumulators
            int g = lane >> 2, tq = lane & 3;
            float* Sp = g_S[chunk];
#pragma unroll
            for (int mt = 0; mt < 2; mt++)
#pragma unroll
                for (int nt = 0; nt < 8; nt++) {
                    int row0 = i0 + mw * 32 + mt * 16 + g;
                    int col = nt * 8 + tq * 2;
                    *(float2*)(Sp + row0 * OUTF + col) =
                        make_float2(acc[mt][nt][0], acc[mt][nt][1]);
                    *(float2*)(Sp + (row0 + 8) * OUTF + col) =
                        make_float2(acc[mt][nt][2], acc[mt][nt][3]);
                }
        }
    }
}

// ---------------- Kernel C: reduce chunks, normalize + ELU ----------------
__global__ void kEpi(float* __restrict__ out) {
    int idx = blockIdx.x * 256 + threadIdx.x;   // NROW*64
    int i = idx >> 6, f = idx & 63;
    float l = 0.f, v = 0.f;
#pragma unroll
    for (int c = 0; c < NCHUNK; c++) {
        l += g_L[c][i];
        v += g_S[c][i * OUTF + f];
    }
    v /= l;
    out[idx] = v > 0.f ? v : expm1f(v);
}

// ---------------- launch ----------------
extern "C" void kernel_launch(void* const* d_in, const int* in_sizes, int n_in,
                              void* d_out, int out_size) {
    (void)in_sizes; (void)n_in; (void)out_size;
    const float* inp = (const float*)d_in[0];
    const int*   adj = (const int*)d_in[1];
    const float* W   = (const float*)d_in[2];
    const float* a   = (const float*)d_in[3];

    cudaFuncSetAttribute(kMain, cudaFuncAttributeMaxDynamicSharedMemorySize, SMEM_BYTES);

    kA<<<NROW / 4, 256>>>(inp, W, a);        // index 0
    kMax<<<1, 256>>>();                      // index 1
    kPad<<<1, 32>>>();                       // index 2
    kMain<<<GRID, 384, SMEM_BYTES>>>(adj);   // index 3  <- ncu capture lands here
    kEpi<<<NROW * OUTF / 256, 256>>>((float*)d_out);
}

// round 10
// speedup vs baseline: 1.8162x; 1.8162x over previous
#include <cuda_runtime.h>
#include <cuda_fp16.h>
#include <cstdint>

#define NROW 12288
#define INF  128
#define OUTF 64
#define LOG2E 1.44269504088896341f
#define NCHUNK 3
#define CT 32                      // tiles per chunk (32*128 = 4096 cols)
#define NITILE (NROW / 128)        // 96
#define NUNITS (NITILE * NCHUNK)   // 288 == grid
#define KC_MAX (CT * 8)            // 256 k-chunks per unit

// smem offsets (dynamic, per CTA)
#define B0   0
#define B1   16384
#define WH2S 32768
#define SMEM_BYTES 49152

// ---------------- device scratch ----------------
__device__ float  g_wh1[NROW];
__device__ float  g_wh2[NROW];
__device__ float  g_wh2max;
__device__ __align__(16) __half g_hT[OUTF * NROW];   // h transposed fp16 [f][j]
__device__ float  g_S[NCHUNK][NROW * OUTF];          // partial E'@h per chunk
__device__ float  g_L[NCHUNK][NROW];                 // partial row sums per chunk

// ---------------- Kernel A: h = input@W, wh1/wh2, hT ----------------
__global__ void kA(const float* __restrict__ inp, const float* __restrict__ W,
                   const float* __restrict__ a) {
    __shared__ float in_s[4][INF];
    __shared__ float red1[8], red2[8];
    int tid = threadIdx.x;
    int i0 = blockIdx.x * 4;
    for (int e = tid; e < 4 * INF; e += 256)
        in_s[e >> 7][e & 127] = inp[(i0 + (e >> 7)) * INF + (e & 127)];
    __syncthreads();
    int f = tid & 63, r = tid >> 6;
    float acc = 0.f;
#pragma unroll 8
    for (int k = 0; k < INF; k++)
        acc = fmaf(in_s[r][k], W[k * OUTF + f], acc);
    int i = i0 + r;
    g_hT[f * NROW + i] = __float2half(acc);
    float p1 = acc * a[f];
    float p2 = acc * a[64 + f];
#pragma unroll
    for (int o = 16; o > 0; o >>= 1) {
        p1 += __shfl_xor_sync(~0u, p1, o);
        p2 += __shfl_xor_sync(~0u, p2, o);
    }
    int w = tid >> 5;
    if ((tid & 31) == 0) { red1[w] = p1; red2[w] = p2; }
    __syncthreads();
    if (tid < 4) {
        g_wh1[i0 + tid] = red1[2 * tid] + red1[2 * tid + 1];
        g_wh2[i0 + tid] = red2[2 * tid] + red2[2 * tid + 1];
    }
}

// ---------------- Kernel A2: global max of wh2 ----------------
__global__ void kMax() {
    __shared__ float red[8];
    int tid = threadIdx.x;
    float m = -1e30f;
    for (int i = tid; i < NROW; i += 256) m = fmaxf(m, g_wh2[i]);
#pragma unroll
    for (int o = 16; o > 0; o >>= 1) m = fmaxf(m, __shfl_xor_sync(~0u, m, o));
    if ((tid & 31) == 0) red[tid >> 5] = m;
    __syncthreads();
    if (tid == 0) {
        float mm = red[0];
#pragma unroll
        for (int w = 1; w < 8; w++) mm = fmaxf(mm, red[w]);
        g_wh2max = mm;
    }
}

// pad so ncu's capture (launch index 3) lands on kMain
__global__ void kPad() {}

// ---------------- Kernel B: homogeneous warps, reg-resident A fragments ----------------
// 256 threads, 2 CTAs/SM. Warp w owns output rows i0 + w*16 .. +15.
// k-slot permutation within each 16-j chunk: slot-word m -> j-word q:
//   q = (m<4) ? 2m : 2(m-4)+1   (so A lanes load adj via one LDG.128 per row)
__global__ void __launch_bounds__(256, 2) kMain(const int* __restrict__ adj) {
    extern __shared__ char smem[];
    uint32_t sb = (uint32_t)__cvta_generic_to_shared(smem);
    float* wh2s = (float*)(smem + WH2S);
    int tid = threadIdx.x, lane = tid & 31, w = tid >> 5;

    int u = blockIdx.x;
    int itile = u / NCHUNK, chunk = u % NCHUNK;
    int i0 = itile * 128;
    long long jbase = (long long)chunk * (CT * 128);

    // stage this unit's wh2 (4096 floats = 16KB)
    {
        const float4* src = (const float4*)(g_wh2 + jbase);
        float4* dst = (float4*)wh2s;
#pragma unroll
        for (int k = 0; k < 4; k++) dst[tid + k * 256] = src[tid + k * 256];
    }

    // per-lane row constants (rows rA, rA+8)
    int rA = i0 + w * 16 + (lane >> 2);
    const float wh2max = g_wh2max;
    float w1a = g_wh1[rA], w1b = g_wh1[rA + 8];
    float sA = w1a + wh2max, sB = w1b + wh2max;
    float m2a = fmaxf(sA, 0.2f * sA) * LOG2E;    // lrelu upper bound of row max
    float m2b = fmaxf(sB, 0.2f * sB) * LOG2E;

    // adj stream pointers: lane covers j = kc*16 + (lane&3)*4 .. +3
    const int* pA = adj + (long long)rA * NROW + jbase + (lane & 3) * 4;
    const int* pB = pA + (long long)8 * NROW;
    int4 avA[2], avB[2];
    avA[0] = __ldcs((const int4*)(pA));
    avB[0] = __ldcs((const int4*)(pB));
    avA[1] = __ldcs((const int4*)(pA + 16));
    avB[1] = __ldcs((const int4*)(pB + 16));

    // B loader: warp w loads n = w + 8s, jq = lane (uint2 = 2 words = 4 halfs)
    const uint2* hT2 = (const uint2*)g_hT;
    long long bcol0 = (jbase >> 2);
    uint2 bw[8];
#pragma unroll
    for (int s = 0; s < 8; s++)
        bw[s] = __ldg(&hT2[(w + 8 * s) * (NROW / 4) + bcol0 + lane]);

    // permuted slot-word indices for the two words of each uint2
    int jp0 = ((lane >> 2) << 3) | (lane & 3);   // word 2*jq (j even pair): m = q/2
    int jp1 = jp0 + 4;                           // word 2*jq+1 (odd): m = 4 + q/2
    uint32_t st_hi0 = (uint32_t)((jp0 >> 2) << 4);
    uint32_t st_lo0 = (uint32_t)((jp0 & 3) * 4);
    uint32_t st_hi1 = (uint32_t)((jp1 >> 2) << 4);
    uint32_t st_lo1 = (uint32_t)((jp1 & 3) * 4);

    // B ldmatrix constants (R6-verified pattern)
    int g2 = lane >> 4, kh = (lane >> 3) & 1, r7 = lane & 7;
    uint32_t brow[4];
#pragma unroll
    for (int nt2 = 0; nt2 < 4; nt2++)
        brow[nt2] = (uint32_t)((nt2 * 16 + g2 * 8 + r7) * 256);
    uint32_t bxor = (uint32_t)(r7 << 1);

    float acc[8][4];
#pragma unroll
    for (int nt = 0; nt < 8; nt++)
#pragma unroll
        for (int q = 0; q < 4; q++) acc[nt][q] = 0.f;
    float fr0 = 0.f, fr8 = 0.f;

    for (int t = 0; t < CT; t++) {
        uint32_t Bbuf = sb + ((t & 1) ? B1 : B0);
        // store B(t) with slot permutation + xor swizzle
#pragma unroll
        for (int s = 0; s < 8; s++) {
            uint32_t n = (uint32_t)(w + 8 * s);
            uint32_t nx = (n & 7) << 1;
            uint32_t base = Bbuf + n * 256;
            uint32_t a0 = base + (((st_hi0 >> 4) ^ nx) << 4) + st_lo0;
            uint32_t a1 = base + (((st_hi1 >> 4) ^ nx) << 4) + st_lo1;
            asm volatile("st.shared.b32 [%0], %1;" :: "r"(a0), "r"(bw[s].x));
            asm volatile("st.shared.b32 [%0], %1;" :: "r"(a1), "r"(bw[s].y));
        }
        __syncthreads();   // B(t) visible; also guarantees all warps done with MMA(t-1)

        // prefetch B(t+1) under this tile's MMA
        if (t + 1 < CT) {
            long long c = bcol0 + (long long)(t + 1) * 32;
#pragma unroll
            for (int s = 0; s < 8; s++)
                bw[s] = __ldg(&hT2[(w + 8 * s) * (NROW / 4) + c + lane]);
        }

#pragma unroll
        for (int ks = 0; ks < 8; ks++) {
            int kc = t * 8 + ks;
            int4 aR = avA[kc & 1], aR8 = avB[kc & 1];
            if (kc + 2 < KC_MAX) {                       // rolling depth-2 adj prefetch
                avA[kc & 1] = __ldcs((const int4*)(pA + (kc + 2) * 16));
                avB[kc & 1] = __ldcs((const int4*)(pB + (kc + 2) * 16));
            }
            float4 wv = *(const float4*)(wh2s + kc * 16 + (lane & 3) * 4);

            // E' directly in mma A-fragment layout (permuted k-slots)
            float s0 = w1a + wv.x, s1 = w1a + wv.y, s2 = w1a + wv.z, s3 = w1a + wv.w;
            float u0 = w1b + wv.x, u1 = w1b + wv.y, u2 = w1b + wv.z, u3 = w1b + wv.w;
            float x0 = fmaf(fmaxf(s0, 0.2f * s0), LOG2E, -m2a);
            float x1 = fmaf(fmaxf(s1, 0.2f * s1), LOG2E, -m2a);
            float x2 = fmaf(fmaxf(s2, 0.2f * s2), LOG2E, -m2a);
            float x3 = fmaf(fmaxf(s3, 0.2f * s3), LOG2E, -m2a);
            float y0 = fmaf(fmaxf(u0, 0.2f * u0), LOG2E, -m2b);
            float y1 = fmaf(fmaxf(u1, 0.2f * u1), LOG2E, -m2b);
            float y2 = fmaf(fmaxf(u2, 0.2f * u2), LOG2E, -m2b);
            float y3 = fmaf(fmaxf(u3, 0.2f * u3), LOG2E, -m2b);
            x0 = aR.x ? x0 : -1e4f;  x1 = aR.y ? x1 : -1e4f;
            x2 = aR.z ? x2 : -1e4f;  x3 = aR.w ? x3 : -1e4f;
            y0 = aR8.x ? y0 : -1e4f; y1 = aR8.y ? y1 : -1e4f;
            y2 = aR8.z ? y2 : -1e4f; y3 = aR8.w ? y3 : -1e4f;
            __half2 hx01 = __floats2half2_rn(x0, x1);
            __half2 hx23 = __floats2half2_rn(x2, x3);
            __half2 hy01 = __floats2half2_rn(y0, y1);
            __half2 hy23 = __floats2half2_rn(y2, y3);
            uint32_t a0, a1, a2, a3;
            asm("ex2.approx.f16x2 %0, %1;" : "=r"(a0) : "r"(*(uint32_t*)&hx01));
            asm("ex2.approx.f16x2 %0, %1;" : "=r"(a1) : "r"(*(uint32_t*)&hy01));
            asm("ex2.approx.f16x2 %0, %1;" : "=r"(a2) : "r"(*(uint32_t*)&hx23));
            asm("ex2.approx.f16x2 %0, %1;" : "=r"(a3) : "r"(*(uint32_t*)&hy23));

            // row-sum accumulation (pairwise half add, then exact float accumulate)
            {
                __half2 hr0 = __hadd2(*(__half2*)&a0, *(__half2*)&a2);
                __half2 hr8 = __hadd2(*(__half2*)&a1, *(__half2*)&a3);
                float2 f0 = __half22float2(hr0);
                float2 f8 = __half22float2(hr8);
                fr0 += f0.x + f0.y;
                fr8 += f8.x + f8.y;
            }

            // B fragments + 8 MMAs
            uint32_t bsw = ((((uint32_t)(ks * 2 + kh)) ^ bxor) << 4);
#pragma unroll
            for (int nt2 = 0; nt2 < 4; nt2++) {
                uint32_t b0, b1, b2, b3;
                asm volatile("ldmatrix.sync.aligned.m8n8.x4.shared.b16 {%0,%1,%2,%3}, [%4];"
                             : "=r"(b0), "=r"(b1), "=r"(b2), "=r"(b3)
                             : "r"(Bbuf + brow[nt2] + bsw));
                int nt = nt2 * 2;
                asm volatile("mma.sync.aligned.m16n8k16.row.col.f32.f16.f16.f32 "
                             "{%0,%1,%2,%3}, {%4,%5,%6,%7}, {%8,%9}, {%0,%1,%2,%3};"
                             : "+f"(acc[nt][0]), "+f"(acc[nt][1]),
                               "+f"(acc[nt][2]), "+f"(acc[nt][3])
                             : "r"(a0), "r"(a1), "r"(a2), "r"(a3), "r"(b0), "r"(b1));
                asm volatile("mma.sync.aligned.m16n8k16.row.col.f32.f16.f16.f32 "
                             "{%0,%1,%2,%3}, {%4,%5,%6,%7}, {%8,%9}, {%0,%1,%2,%3};"
                             : "+f"(acc[nt + 1][0]), "+f"(acc[nt + 1][1]),
                               "+f"(acc[nt + 1][2]), "+f"(acc[nt + 1][3])
                             : "r"(a0), "r"(a1), "r"(a2), "r"(a3), "r"(b2), "r"(b3));
            }
        }
    }

    // ---- writeback accumulators ----
    {
        int row0 = i0 + w * 16 + (lane >> 2);
        int colb = (lane & 3) * 2;
        float* Sp = g_S[chunk];
#pragma unroll
        for (int nt = 0; nt < 8; nt++) {
            *(float2*)(Sp + row0 * OUTF + nt * 8 + colb) =
                make_float2(acc[nt][0], acc[nt][1]);
            *(float2*)(Sp + (row0 + 8) * OUTF + nt * 8 + colb) =
                make_float2(acc[nt][2], acc[nt][3]);
        }
    }
    // ---- row sums: reduce within c-quad ----
    fr0 += __shfl_xor_sync(~0u, fr0, 1);
    fr0 += __shfl_xor_sync(~0u, fr0, 2);
    fr8 += __shfl_xor_sync(~0u, fr8, 1);
    fr8 += __shfl_xor_sync(~0u, fr8, 2);
    if ((lane & 3) == 0) {
        g_L[chunk][rA] = fr0;
        g_L[chunk][rA + 8] = fr8;
    }
}

// ---------------- Kernel C: reduce chunks, normalize + ELU ----------------
__global__ void kEpi(float* __restrict__ out) {
    int idx = blockIdx.x * 256 + threadIdx.x;   // NROW*64
    int i = idx >> 6, f = idx & 63;
    float l = 0.f, v = 0.f;
#pragma unroll
    for (int c = 0; c < NCHUNK; c++) {
        l += g_L[c][i];
        v += g_S[c][i * OUTF + f];
    }
    v /= l;
    out[idx] = v > 0.f ? v : expm1f(v);
}

// ---------------- launch ----------------
extern "C" void kernel_launch(void* const* d_in, const int* in_sizes, int n_in,
                              void* d_out, int out_size) {
    (void)in_sizes; (void)n_in; (void)out_size;
    const float* inp = (const float*)d_in[0];
    const int*   adj = (const int*)d_in[1];
    const float* W   = (const float*)d_in[2];
    const float* a   = (const float*)d_in[3];

    cudaFuncSetAttribute(kMain, cudaFuncAttributeMaxDynamicSharedMemorySize, SMEM_BYTES);

    kA<<<NROW / 4, 256>>>(inp, W, a);           // index 0
    kMax<<<1, 256>>>();                         // index 1
    kPad<<<1, 32>>>();                          // index 2
    kMain<<<NUNITS, 256, SMEM_BYTES>>>(adj);    // index 3  <- ncu capture
    kEpi<<<NROW * OUTF / 256, 256>>>((float*)d_out);
}